// round 10
// baseline (speedup 1.0000x reference)
#include <cuda_runtime.h>
#include <cuda_fp16.h>

typedef unsigned long long ull;

// Problem constants (fixed by the dataset)
#define BB 32
#define NN 200
#define DD 100
#define IT 8              // i-rows per block
#define C14 14            // 8-half d-chunks per row (112 padded)
#define PTS 12            // pt row stride (floats)
#define STGS 104          // staging row stride (floats)
#define NEGV (-9e15f)

// smem (floats): g_frag(fp16) | pt | stg
#define GFRAG_HALVES (2*7*32*8)              // [mt][ks][lane][8 halves] = 3584
#define OFF_PT  (GFRAG_HALVES/2)             // 1792 floats
#define OFF_STG (OFF_PT + NN*PTS)            // + 2400
#define SMEM_FLOATS (OFF_STG + IT*IT*STGS)   // + 6656 = 10848
#define SMEM_BYTES  (SMEM_FLOATS*4)          // 43392 B

// packed f32x2 ops (SASS FFMA2 / FADD-pair)
#define FMA2(d, a, b, c) \
    asm("fma.rn.f32x2 %0, %1, %2, %3;" : "=l"(d) : "l"(a), "l"(b), "l"(c))
#define ADD2(d, a, b) \
    asm("add.rn.f32x2 %0, %1, %2;" : "=l"(d) : "l"(a), "l"(b))

__device__ __forceinline__ ull pack_dup(float v) {
    ull r;
    asm("mov.b64 %0, {%1, %1};" : "=l"(r) : "f"(v));
    return r;
}

// fp16 transposed gathered embeddings: ht[b][c14][j][8 halves]
__device__ __half ht_scratch[(size_t)BB * C14 * NN * 8];
// fp16 edge weights: ah[c14][k][8 halves]
__device__ __half ah_scratch[C14 * 4 * 8];

__global__ void transpose_kernel(const int* __restrict__ inputs,
                                 const float* __restrict__ emb,
                                 const float* __restrict__ a0,
                                 const float* __restrict__ a1,
                                 const float* __restrict__ a2,
                                 const float* __restrict__ a3)
{
    const int c = blockIdx.x;      // 0..13
    const int b = blockIdx.y;      // batch
    const int j = threadIdx.x;     // 0..255, 200 active
    if (j < NN) {
        int id = inputs[b * NN + j];
        const float* src = emb + (size_t)id * DD;
        __half h[8];
#pragma unroll
        for (int r = 0; r < 8; ++r) {
            int d = c * 8 + r;
            h[r] = __float2half(d < DD ? src[d] : 0.f);
        }
        *(uint4*)(ht_scratch + (((size_t)b * C14 + c) * NN + j) * 8) = *(uint4*)h;
    }
    if (b == 0 && j < 4) {
        const float* ak = (j == 0) ? a0 : (j == 1) ? a1 : (j == 2) ? a2 : a3;
        __half h[8];
#pragma unroll
        for (int r = 0; r < 8; ++r) {
            int d = c * 8 + r;
            h[r] = __float2half(d < DD ? ak[d] : 0.f);
        }
        *(uint4*)(ah_scratch + (c * 4 + j) * 8) = *(uint4*)h;
    }
}

__global__ __launch_bounds__(256, 4)
void gnn_agg_kernel(const int* __restrict__ inputs,
                    const int* __restrict__ adj,
                    const float* __restrict__ emb,
                    float* __restrict__ out)
{
    extern __shared__ float sm[];
    __half* gf = (__half*)sm;        // A fragments: [(mt*7+ks)*32+lane][8 halves]
    float* pt  = sm + OFF_PT;        // [NN][PTS] (first 8 used): alpha -> p
    float* stg = sm + OFF_STG;       // [IT writers][IT i][STGS]
    __shared__ int ids[NN];
    __shared__ int kb_s[NN];         // nibble i: ksel(2b) | valid(bit2)

    const int b    = blockIdx.y;
    const int i0   = blockIdx.x * IT;
    const int tid  = threadIdx.x;
    const int w    = tid >> 5;
    const int lane = tid & 31;
    const int gid  = lane >> 2;      // 0..7
    const int tig  = lane & 3;       // 0..3

    // ---- ids + kb table ----
    if (tid < NN) {
        ids[tid] = inputs[b * NN + tid];
        unsigned kb = 0;
        const int* ap = adj + ((size_t)b * NN + i0) * NN + tid;
#pragma unroll
        for (int i = 0; i < IT; ++i) {
            int a = ap[(size_t)i * NN];
            unsigned valid = (a >= 1 && a <= 4) ? 4u : 0u;
            unsigned ksel = valid ? (unsigned)(a - 1) : 0u;
            kb |= (ksel | valid) << (4 * i);
        }
        kb_s[tid] = (int)kb;
    }

    // ---- pt pre-init to NEG ----
    for (int u = tid; u < NN * 8; u += 256) {
        int jj = u >> 3, ii = u & 7;
        pt[jj * PTS + ii] = NEGV;
    }

    // ---- stage A fragments: gf[mt][ks][lane] = 4 half2 in m16n8k16 A order ----
    // row r of tile mt: k = 2*mt + r/8, i = r%8 ; value = h_i[d] * a_k[d]
    for (int e = tid; e < 448; e += 256) {
        int mt = e / 224, rem = e - mt * 224;
        int ks = rem >> 5, l = rem & 31;
        int g8 = l >> 2, t4 = l & 3;
        int i  = i0 + g8;
        int cp = t4 * 2;                  // col pair base within k16
        int c8a = 2 * ks, c8b = 2 * ks + 1;
        __half2 hlo = *(const __half2*)(ht_scratch + (((size_t)b * C14 + c8a) * NN + i) * 8 + cp);
        __half2 hhi = *(const __half2*)(ht_scratch + (((size_t)b * C14 + c8b) * NN + i) * 8 + cp);
        int ka = 2 * mt, kb2 = 2 * mt + 1;
        __half2 alo_a = *(const __half2*)(ah_scratch + (c8a * 4 + ka)  * 8 + cp);
        __half2 alo_b = *(const __half2*)(ah_scratch + (c8a * 4 + kb2) * 8 + cp);
        __half2 ahi_a = *(const __half2*)(ah_scratch + (c8b * 4 + ka)  * 8 + cp);
        __half2 ahi_b = *(const __half2*)(ah_scratch + (c8b * 4 + kb2) * 8 + cp);
        __half2 r0 = __hmul2(hlo, alo_a);   // (row g8,   cols cp,cp+1)  k = ka
        __half2 r1 = __hmul2(hlo, alo_b);   // (row g8+8, cols cp,cp+1)  k = kb
        __half2 r2 = __hmul2(hhi, ahi_a);   // (row g8,   cols cp+8,+9)  k = ka
        __half2 r3 = __hmul2(hhi, ahi_b);   // (row g8+8, cols cp+8,+9)  k = kb
        __half2 pk[4] = {r0, r1, r2, r3};
        *(uint4*)(gf + (size_t)(mt * 7 + ks) * 32 * 8 + l * 8) = *(uint4*)pk;
    }
    __syncthreads();

    // ---- score via HMMA: C[32=(k,i), 200=j] ----
    const int mt = w & 1;
    // preload 7 A fragments (28 regs)
    unsigned aF[7][4];
#pragma unroll
    for (int ks = 0; ks < 7; ++ks)
        *(uint4*)aF[ks] = *(const uint4*)(gf + (size_t)(mt * 7 + ks) * 32 * 8 + lane * 8);

    const __half* htb = ht_scratch + (size_t)b * C14 * NN * 8;
    for (int nt = (w >> 1); nt < 25; nt += 4) {
        float c0 = 0.f, c1 = 0.f, c2 = 0.f, c3 = 0.f;
        int jB = nt * 8 + gid;           // B-frag column for this lane
#pragma unroll
        for (int ks = 0; ks < 7; ++ks) {
            unsigned b0 = *(const unsigned*)(htb + ((size_t)(2 * ks)     * NN + jB) * 8 + tig * 2);
            unsigned b1 = *(const unsigned*)(htb + ((size_t)(2 * ks + 1) * NN + jB) * 8 + tig * 2);
            asm("mma.sync.aligned.m16n8k16.row.col.f32.f16.f16.f32 "
                "{%0,%1,%2,%3}, {%4,%5,%6,%7}, {%8,%9}, {%0,%1,%2,%3};"
                : "+f"(c0), "+f"(c1), "+f"(c2), "+f"(c3)
                : "r"(aF[ks][0]), "r"(aF[ks][1]), "r"(aF[ks][2]), "r"(aF[ks][3]),
                  "r"(b0), "r"(b1));
        }
        // epilogue: lane holds (k=2mt, i=gid, j), (k=2mt, i, j+1), (k=2mt+1, i, j), (k=2mt+1, i, j+1)
        int j0 = nt * 8 + tig * 2;
        unsigned k0 = (unsigned)kb_s[j0]     >> (4 * gid);
        unsigned k1 = (unsigned)kb_s[j0 + 1] >> (4 * gid);
        unsigned ka = (unsigned)(2 * mt), kbv = ka + 1;
        if ((k0 & 4u) && (k0 & 3u) == ka)  pt[j0 * PTS + gid]       = (c0 >= 0.f) ? c0 : 0.2f * c0;
        if ((k1 & 4u) && (k1 & 3u) == ka)  pt[(j0 + 1) * PTS + gid] = (c1 >= 0.f) ? c1 : 0.2f * c1;
        if ((k0 & 4u) && (k0 & 3u) == kbv) pt[j0 * PTS + gid]       = (c2 >= 0.f) ? c2 : 0.2f * c2;
        if ((k1 & 4u) && (k1 & 3u) == kbv) pt[(j0 + 1) * PTS + gid] = (c3 >= 0.f) ? c3 : 0.2f * c3;
    }
    __syncthreads();

    // ---- softmax: warp w owns row i = w ----
    {
        float al[7];
#pragma unroll
        for (int t = 0; t < 7; ++t) {
            int jj = lane + 32 * t;
            al[t] = (jj < NN) ? pt[jj * PTS + w] : NEGV;
        }
        float m = al[0];
#pragma unroll
        for (int t = 1; t < 7; ++t) m = fmaxf(m, al[t]);
#pragma unroll
        for (int off = 16; off > 0; off >>= 1)
            m = fmaxf(m, __shfl_xor_sync(0xffffffffu, m, off));

        float pv[7];
        float sum = 0.f;
#pragma unroll
        for (int t = 0; t < 7; ++t) {
            int jj = lane + 32 * t;
            float e = (jj < NN) ? __expf(al[t] - m) : 0.f;
            pv[t] = e;
            sum += e;
        }
#pragma unroll
        for (int off = 16; off > 0; off >>= 1)
            sum += __shfl_xor_sync(0xffffffffu, sum, off);
        float rinv = 1.f / sum;
#pragma unroll
        for (int t = 0; t < 7; ++t) {
            int jj = lane + 32 * t;
            if (jj < NN) pt[jj * PTS + w] = pv[t] * rinv;
        }
    }
    __syncthreads();

    // ---- aggregation (fp32): warp w streams its 25 j rows from L2 ----
    const bool act = (lane < 25);
    ull acc0[IT], acc1[IT];
#pragma unroll
    for (int i = 0; i < IT; ++i) { acc0[i] = 0ull; acc1[i] = 0ull; }

    const int dl = act ? lane : 24;   // lane owns d-chunk 4*dl
#pragma unroll 5
    for (int jj = 0; jj < 25; ++jj) {
        int jb = w * 25 + jj;
        const float* hj = emb + (size_t)ids[jb] * DD;         // ids broadcast LDS
        ulonglong2 hv = *(const ulonglong2*)(hj + 4 * dl);    // L2-hot LDG.128
        float4 pA = *(const float4*)(pt + jb * PTS);          // p[i=0..3] broadcast
        float4 pB = *(const float4*)(pt + jb * PTS + 4);      // p[i=4..7] broadcast
        ull q;
        q = pack_dup(pA.x); FMA2(acc0[0], q, hv.x, acc0[0]); FMA2(acc1[0], q, hv.y, acc1[0]);
        q = pack_dup(pA.y); FMA2(acc0[1], q, hv.x, acc0[1]); FMA2(acc1[1], q, hv.y, acc1[1]);
        q = pack_dup(pA.z); FMA2(acc0[2], q, hv.x, acc0[2]); FMA2(acc1[2], q, hv.y, acc1[2]);
        q = pack_dup(pA.w); FMA2(acc0[3], q, hv.x, acc0[3]); FMA2(acc1[3], q, hv.y, acc1[3]);
        q = pack_dup(pB.x); FMA2(acc0[4], q, hv.x, acc0[4]); FMA2(acc1[4], q, hv.y, acc1[4]);
        q = pack_dup(pB.y); FMA2(acc0[5], q, hv.x, acc0[5]); FMA2(acc1[5], q, hv.y, acc1[5]);
        q = pack_dup(pB.z); FMA2(acc0[6], q, hv.x, acc0[6]); FMA2(acc1[6], q, hv.y, acc1[6]);
        q = pack_dup(pB.w); FMA2(acc0[7], q, hv.x, acc0[7]); FMA2(acc1[7], q, hv.y, acc1[7]);
    }

    // ---- parallel cross-warp reduce: everyone stages, warp w reduces row i=w ----
    if (act) {
#pragma unroll
        for (int i = 0; i < IT; ++i) {
            ulonglong2 v; v.x = acc0[i]; v.y = acc1[i];
            *(ulonglong2*)(stg + (w * IT + i) * STGS + 4 * lane) = v;
        }
    }
    __syncthreads();

    if (act) {
        ull r0 = 0ull, r1 = 0ull;
#pragma unroll
        for (int ww = 0; ww < IT; ++ww) {
            ulonglong2 v = *(const ulonglong2*)(stg + (ww * IT + w) * STGS + 4 * lane);
            ADD2(r0, r0, v.x);
            ADD2(r1, r1, v.y);
        }
        ulonglong2 o; o.x = r0; o.y = r1;
        *(ulonglong2*)(out + ((size_t)(b * NN + i0 + w)) * DD + 4 * lane) = o;
    }
}

extern "C" void kernel_launch(void* const* d_in, const int* in_sizes, int n_in,
                              void* d_out, int out_size)
{
    const int*   inputs = (const int*)d_in[0];
    const int*   adj    = (const int*)d_in[1];
    // d_in[2] = mask_item (unused by reference)
    const float* emb    = (const float*)d_in[3];
    const float* a0     = (const float*)d_in[4];
    const float* a1     = (const float*)d_in[5];
    const float* a2     = (const float*)d_in[6];
    const float* a3     = (const float*)d_in[7];
    float*       out    = (float*)d_out;

    cudaFuncSetAttribute(gnn_agg_kernel,
                         cudaFuncAttributeMaxDynamicSharedMemorySize,
                         SMEM_BYTES);

    // Phase 1: gather + transpose h (and a) into fp16 scratch (112-d padded)
    dim3 tg(C14, BB);    // 14 x 32
    transpose_kernel<<<tg, 256>>>(inputs, emb, a0, a1, a2, a3);

    // Phase 2: fused HMMA-score / softmax / aggregate
    dim3 grid(NN / IT, BB);   // 25 x 32 = 800 blocks
    gnn_agg_kernel<<<grid, 256, SMEM_BYTES>>>(inputs, adj, emb, out);
}

// round 11
// speedup vs baseline: 1.3350x; 1.3350x over previous
#include <cuda_runtime.h>
#include <cuda_fp16.h>

typedef unsigned long long ull;

// Problem constants (fixed by the dataset)
#define BB 32
#define NN 200
#define DD 100
#define IT 8              // i-rows per block
#define C14 14            // 8-half d-chunks per row (112 padded)
#define PTS 12            // pt row stride (floats)
#define STGS 104          // staging row stride (floats)
#define NEGV (-9e15f)

// smem (floats): gf(fp16) | pt(f32) | ph(fp16) | stg
#define OFF_PT  1792                         // gf: 2*7*32*8 halves = 1792 floats
#define OFF_PH  (OFF_PT + NN*PTS)            // pt: 2400 floats
#define OFF_STG (OFF_PH + NN*4)              // ph: NN*8 halves = 800 floats
#define SMEM_FLOATS (OFF_STG + IT*IT*STGS)   // stg: 6656 -> total 11648
#define SMEM_BYTES  (SMEM_FLOATS*4)          // 46592 B

// packed f32x2 ops (SASS FFMA2 / FADD-pair)
#define FMA2(d, a, b, c) \
    asm("fma.rn.f32x2 %0, %1, %2, %3;" : "=l"(d) : "l"(a), "l"(b), "l"(c))
#define ADD2(d, a, b) \
    asm("add.rn.f32x2 %0, %1, %2;" : "=l"(d) : "l"(a), "l"(b))

__device__ __forceinline__ ull pack_dup(float v) {
    ull r;
    asm("mov.b64 %0, {%1, %1};" : "=l"(r) : "f"(v));
    return r;
}

// fp16 transposed gathered embeddings: ht[b][c14][j][8 halves]
__device__ __half ht_scratch[(size_t)BB * C14 * NN * 8];
// fp16 edge weights: ah[c14][k][8 halves]
__device__ __half ah_scratch[C14 * 4 * 8];

__global__ void transpose_kernel(const int* __restrict__ inputs,
                                 const float* __restrict__ emb,
                                 const float* __restrict__ a0,
                                 const float* __restrict__ a1,
                                 const float* __restrict__ a2,
                                 const float* __restrict__ a3)
{
    const int c = blockIdx.x;      // 0..13
    const int b = blockIdx.y;      // batch
    const int j = threadIdx.x;     // 0..255, 200 active
    if (j < NN) {
        int id = inputs[b * NN + j];
        const float* src = emb + (size_t)id * DD;
        __half h[8];
#pragma unroll
        for (int r = 0; r < 8; ++r) {
            int d = c * 8 + r;
            h[r] = __float2half(d < DD ? src[d] : 0.f);
        }
        *(uint4*)(ht_scratch + (((size_t)b * C14 + c) * NN + j) * 8) = *(uint4*)h;
    }
    if (b == 0 && j < 4) {
        const float* ak = (j == 0) ? a0 : (j == 1) ? a1 : (j == 2) ? a2 : a3;
        __half h[8];
#pragma unroll
        for (int r = 0; r < 8; ++r) {
            int d = c * 8 + r;
            h[r] = __float2half(d < DD ? ak[d] : 0.f);
        }
        *(uint4*)(ah_scratch + (c * 4 + j) * 8) = *(uint4*)h;
    }
}

__global__ __launch_bounds__(256, 3)
void gnn_agg_kernel(const int* __restrict__ inputs,
                    const int* __restrict__ adj,
                    const float* __restrict__ emb,
                    float* __restrict__ out)
{
    extern __shared__ float sm[];
    __half* gf = (__half*)sm;        // A fragments: [(mt*7+ks)*32+lane][8 halves]
    float*  pt = sm + OFF_PT;        // [NN][PTS] (first 8 used): alpha staging
    __half* ph = (__half*)(sm + OFF_PH);  // [NN][8]: fp16 softmax weights
    float* stg = sm + OFF_STG;       // [IT writers][IT i][STGS]
    __shared__ int ids[NN];
    __shared__ int kb_s[NN];         // nibble i: ksel(2b) | valid(bit2)

    const int b    = blockIdx.y;
    const int i0   = blockIdx.x * IT;
    const int tid  = threadIdx.x;
    const int w    = tid >> 5;
    const int lane = tid & 31;
    const int gid  = lane >> 2;      // 0..7
    const int tig  = lane & 3;       // 0..3

    // ---- ids + kb table ----
    if (tid < NN) {
        ids[tid] = inputs[b * NN + tid];
        unsigned kb = 0;
        const int* ap = adj + ((size_t)b * NN + i0) * NN + tid;
#pragma unroll
        for (int i = 0; i < IT; ++i) {
            int a = ap[(size_t)i * NN];
            unsigned valid = (a >= 1 && a <= 4) ? 4u : 0u;
            unsigned ksel = valid ? (unsigned)(a - 1) : 0u;
            kb |= (ksel | valid) << (4 * i);
        }
        kb_s[tid] = (int)kb;
    }

    // ---- pt pre-init to NEG ----
    for (int u = tid; u < NN * 8; u += 256) {
        int jj = u >> 3, ii = u & 7;
        pt[jj * PTS + ii] = NEGV;
    }

    // ---- stage A fragments: gf[mt][ks][lane] = 4 half2 in m16n8k16 A order ----
    for (int e = tid; e < 448; e += 256) {
        int mt = e / 224, rem = e - mt * 224;
        int ks = rem >> 5, l = rem & 31;
        int g8 = l >> 2, t4 = l & 3;
        int i  = i0 + g8;
        int cp = t4 * 2;
        int c8a = 2 * ks, c8b = 2 * ks + 1;
        __half2 hlo = *(const __half2*)(ht_scratch + (((size_t)b * C14 + c8a) * NN + i) * 8 + cp);
        __half2 hhi = *(const __half2*)(ht_scratch + (((size_t)b * C14 + c8b) * NN + i) * 8 + cp);
        int ka = 2 * mt, kb2 = 2 * mt + 1;
        __half2 alo_a = *(const __half2*)(ah_scratch + (c8a * 4 + ka)  * 8 + cp);
        __half2 alo_b = *(const __half2*)(ah_scratch + (c8a * 4 + kb2) * 8 + cp);
        __half2 ahi_a = *(const __half2*)(ah_scratch + (c8b * 4 + ka)  * 8 + cp);
        __half2 ahi_b = *(const __half2*)(ah_scratch + (c8b * 4 + kb2) * 8 + cp);
        __half2 pk[4];
        pk[0] = __hmul2(hlo, alo_a);
        pk[1] = __hmul2(hlo, alo_b);
        pk[2] = __hmul2(hhi, ahi_a);
        pk[3] = __hmul2(hhi, ahi_b);
        *(uint4*)(gf + (size_t)(mt * 7 + ks) * 32 * 8 + l * 8) = *(uint4*)pk;
    }
    __syncthreads();

    // ---- score via HMMA: C[32=(k,i), 200=j], split even/odd-ks chains ----
    const int mt = w & 1;
    unsigned aF[7][4];
#pragma unroll
    for (int ks = 0; ks < 7; ++ks)
        *(uint4*)aF[ks] = *(const uint4*)(gf + (size_t)(mt * 7 + ks) * 32 * 8 + lane * 8);

    const __half* htb = ht_scratch + (size_t)b * C14 * NN * 8;
    for (int nt = (w >> 1); nt < 25; nt += 4) {
        int jB = nt * 8 + gid;
        // prefetch all 14 B fragments (coalesced LDG.32)
        unsigned b0[7], b1[7];
#pragma unroll
        for (int ks = 0; ks < 7; ++ks) {
            b0[ks] = *(const unsigned*)(htb + ((size_t)(2 * ks)     * NN + jB) * 8 + tig * 2);
            b1[ks] = *(const unsigned*)(htb + ((size_t)(2 * ks + 1) * NN + jB) * 8 + tig * 2);
        }
        // two independent accumulator chains (even ks / odd ks)
        float cA0 = 0.f, cA1 = 0.f, cA2 = 0.f, cA3 = 0.f;
        float cB0 = 0.f, cB1 = 0.f, cB2 = 0.f, cB3 = 0.f;
#pragma unroll
        for (int ks = 0; ks < 7; ks += 2) {
            asm("mma.sync.aligned.m16n8k16.row.col.f32.f16.f16.f32 "
                "{%0,%1,%2,%3}, {%4,%5,%6,%7}, {%8,%9}, {%0,%1,%2,%3};"
                : "+f"(cA0), "+f"(cA1), "+f"(cA2), "+f"(cA3)
                : "r"(aF[ks][0]), "r"(aF[ks][1]), "r"(aF[ks][2]), "r"(aF[ks][3]),
                  "r"(b0[ks]), "r"(b1[ks]));
        }
#pragma unroll
        for (int ks = 1; ks < 7; ks += 2) {
            asm("mma.sync.aligned.m16n8k16.row.col.f32.f16.f16.f32 "
                "{%0,%1,%2,%3}, {%4,%5,%6,%7}, {%8,%9}, {%0,%1,%2,%3};"
                : "+f"(cB0), "+f"(cB1), "+f"(cB2), "+f"(cB3)
                : "r"(aF[ks][0]), "r"(aF[ks][1]), "r"(aF[ks][2]), "r"(aF[ks][3]),
                  "r"(b0[ks]), "r"(b1[ks]));
        }
        float c0 = cA0 + cB0, c1 = cA1 + cB1;
        float c2 = cA2 + cB2, c3 = cA3 + cB3;
        // epilogue: lane holds (k=2mt,i=gid,j0), (k=2mt,i,j0+1), (k=2mt+1,i,j0), (k=2mt+1,i,j0+1)
        int j0 = nt * 8 + tig * 2;
        unsigned k0 = (unsigned)kb_s[j0]     >> (4 * gid);
        unsigned k1 = (unsigned)kb_s[j0 + 1] >> (4 * gid);
        unsigned ka = (unsigned)(2 * mt), kbv = ka + 1;
        if ((k0 & 4u) && (k0 & 3u) == ka)  pt[j0 * PTS + gid]       = (c0 >= 0.f) ? c0 : 0.2f * c0;
        if ((k1 & 4u) && (k1 & 3u) == ka)  pt[(j0 + 1) * PTS + gid] = (c1 >= 0.f) ? c1 : 0.2f * c1;
        if ((k0 & 4u) && (k0 & 3u) == kbv) pt[j0 * PTS + gid]       = (c2 >= 0.f) ? c2 : 0.2f * c2;
        if ((k1 & 4u) && (k1 & 3u) == kbv) pt[(j0 + 1) * PTS + gid] = (c3 >= 0.f) ? c3 : 0.2f * c3;
    }
    __syncthreads();

    // ---- softmax: warp w owns row i = w; writes fp16 weights to ph ----
    {
        float al[7];
#pragma unroll
        for (int t = 0; t < 7; ++t) {
            int jj = lane + 32 * t;
            al[t] = (jj < NN) ? pt[jj * PTS + w] : NEGV;
        }
        float m = al[0];
#pragma unroll
        for (int t = 1; t < 7; ++t) m = fmaxf(m, al[t]);
#pragma unroll
        for (int off = 16; off > 0; off >>= 1)
            m = fmaxf(m, __shfl_xor_sync(0xffffffffu, m, off));

        float pv[7];
        float sum = 0.f;
#pragma unroll
        for (int t = 0; t < 7; ++t) {
            int jj = lane + 32 * t;
            float e = (jj < NN) ? __expf(al[t] - m) : 0.f;
            pv[t] = e;
            sum += e;
        }
#pragma unroll
        for (int off = 16; off > 0; off >>= 1)
            sum += __shfl_xor_sync(0xffffffffu, sum, off);
        float rinv = 1.f / sum;
#pragma unroll
        for (int t = 0; t < 7; ++t) {
            int jj = lane + 32 * t;
            if (jj < NN) ph[jj * 8 + w] = __float2half(pv[t] * rinv);
        }
    }
    __syncthreads();

    // ---- aggregation (fp32 accum): warp w streams its 25 j rows from L2 ----
    const bool act = (lane < 25);
    ull acc0[IT], acc1[IT];
#pragma unroll
    for (int i = 0; i < IT; ++i) { acc0[i] = 0ull; acc1[i] = 0ull; }

    const int dl = act ? lane : 24;   // lane owns d-chunk 4*dl
#pragma unroll 5
    for (int jj = 0; jj < 25; ++jj) {
        int jb = w * 25 + jj;
        const float* hj = emb + (size_t)ids[jb] * DD;         // ids broadcast LDS
        ulonglong2 hv = *(const ulonglong2*)(hj + 4 * dl);    // L2-hot LDG.128
        // p for all 8 i in ONE broadcast LDS.128 (fp16 half8)
        uint4 praw = *(const uint4*)(ph + jb * 8);
        __half2 hp[4];
        *(uint4*)hp = praw;
        float2 f01 = __half22float2(hp[0]);
        float2 f23 = __half22float2(hp[1]);
        float2 f45 = __half22float2(hp[2]);
        float2 f67 = __half22float2(hp[3]);
        ull q;
        q = pack_dup(f01.x); FMA2(acc0[0], q, hv.x, acc0[0]); FMA2(acc1[0], q, hv.y, acc1[0]);
        q = pack_dup(f01.y); FMA2(acc0[1], q, hv.x, acc0[1]); FMA2(acc1[1], q, hv.y, acc1[1]);
        q = pack_dup(f23.x); FMA2(acc0[2], q, hv.x, acc0[2]); FMA2(acc1[2], q, hv.y, acc1[2]);
        q = pack_dup(f23.y); FMA2(acc0[3], q, hv.x, acc0[3]); FMA2(acc1[3], q, hv.y, acc1[3]);
        q = pack_dup(f45.x); FMA2(acc0[4], q, hv.x, acc0[4]); FMA2(acc1[4], q, hv.y, acc1[4]);
        q = pack_dup(f45.y); FMA2(acc0[5], q, hv.x, acc0[5]); FMA2(acc1[5], q, hv.y, acc1[5]);
        q = pack_dup(f67.x); FMA2(acc0[6], q, hv.x, acc0[6]); FMA2(acc1[6], q, hv.y, acc1[6]);
        q = pack_dup(f67.y); FMA2(acc0[7], q, hv.x, acc0[7]); FMA2(acc1[7], q, hv.y, acc1[7]);
    }

    // ---- parallel cross-warp reduce: everyone stages, warp w reduces row i=w ----
    if (act) {
#pragma unroll
        for (int i = 0; i < IT; ++i) {
            ulonglong2 v; v.x = acc0[i]; v.y = acc1[i];
            *(ulonglong2*)(stg + (w * IT + i) * STGS + 4 * lane) = v;
        }
    }
    __syncthreads();

    if (act) {
        ull r0 = 0ull, r1 = 0ull;
#pragma unroll
        for (int ww = 0; ww < IT; ++ww) {
            ulonglong2 v = *(const ulonglong2*)(stg + (ww * IT + w) * STGS + 4 * lane);
            ADD2(r0, r0, v.x);
            ADD2(r1, r1, v.y);
        }
        ulonglong2 o; o.x = r0; o.y = r1;
        *(ulonglong2*)(out + ((size_t)(b * NN + i0 + w)) * DD + 4 * lane) = o;
    }
}

extern "C" void kernel_launch(void* const* d_in, const int* in_sizes, int n_in,
                              void* d_out, int out_size)
{
    const int*   inputs = (const int*)d_in[0];
    const int*   adj    = (const int*)d_in[1];
    // d_in[2] = mask_item (unused by reference)
    const float* emb    = (const float*)d_in[3];
    const float* a0     = (const float*)d_in[4];
    const float* a1     = (const float*)d_in[5];
    const float* a2     = (const float*)d_in[6];
    const float* a3     = (const float*)d_in[7];
    float*       out    = (float*)d_out;

    cudaFuncSetAttribute(gnn_agg_kernel,
                         cudaFuncAttributeMaxDynamicSharedMemorySize,
                         SMEM_BYTES);

    // Phase 1: gather + transpose h (and a) into fp16 scratch (112-d padded)
    dim3 tg(C14, BB);    // 14 x 32
    transpose_kernel<<<tg, 256>>>(inputs, emb, a0, a1, a2, a3);

    // Phase 2: fused HMMA-score / softmax / aggregate
    dim3 grid(NN / IT, BB);   // 25 x 32 = 800 blocks
    gnn_agg_kernel<<<grid, 256, SMEM_BYTES>>>(inputs, adj, emb, out);
}

// round 12
// speedup vs baseline: 1.4287x; 1.0702x over previous
#include <cuda_runtime.h>
#include <cuda_fp16.h>

typedef unsigned long long ull;

// Problem constants (fixed by the dataset)
#define BB 32
#define NN 200
#define DD 100
#define IT 8              // i-rows per block
#define C14 14            // 8-half d-chunks per row (112 padded, score K)
#define DPAD 104          // padded d rows in htd
#define JPAD 208          // padded j cols in htd / pp (13 k16 tiles)
#define PTS 12            // pt row stride (floats)
#define PPS 216           // pp row stride (halves): gid*108%32 walk -> conflict-free
#define NEGV (-9e15f)

// smem (floats): gf(fp16) | pt(f32) | pp(fp16)
#define OFF_PT  1792                         // gf: 2*7*32*8 halves = 1792 floats
#define OFF_PP  (OFF_PT + NN*PTS)            // pt: 2400 floats
#define SMEM_FLOATS (OFF_PP + (8*PPS)/2)     // pp: 1728 halves = 864 floats
#define SMEM_BYTES  (SMEM_FLOATS*4)          // 20224 B

// fp16 transposed gathered embeddings: ht[b][c14][j][8 halves]
__device__ __half ht_scratch[(size_t)BB * C14 * NN * 8];
// fp16 edge weights: ah[c14][k][8 halves]
__device__ __half ah_scratch[C14 * 4 * 8];
// fp16 d-major embeddings for agg B-fragments: htd[b][d][j]
__device__ __half htd_scratch[(size_t)BB * DPAD * JPAD];

__global__ void transpose_kernel(const int* __restrict__ inputs,
                                 const float* __restrict__ emb,
                                 const float* __restrict__ a0,
                                 const float* __restrict__ a1,
                                 const float* __restrict__ a2,
                                 const float* __restrict__ a3)
{
    const int c = blockIdx.x;      // 0..13
    const int b = blockIdx.y;      // batch
    const int j = threadIdx.x;     // 0..255, 200 active
    if (j < NN) {
        int id = inputs[b * NN + j];
        const float* src = emb + (size_t)id * DD;
        __half h[8];
#pragma unroll
        for (int r = 0; r < 8; ++r) {
            int d = c * 8 + r;
            h[r] = __float2half(d < DD ? src[d] : 0.f);
        }
        *(uint4*)(ht_scratch + (((size_t)b * C14 + c) * NN + j) * 8) = *(uint4*)h;
    }
    if (b == 0 && j < 4) {
        const float* ak = (j == 0) ? a0 : (j == 1) ? a1 : (j == 2) ? a2 : a3;
        __half h[8];
#pragma unroll
        for (int r = 0; r < 8; ++r) {
            int d = c * 8 + r;
            h[r] = __float2half(d < DD ? ak[d] : 0.f);
        }
        *(uint4*)(ah_scratch + (c * 4 + j) * 8) = *(uint4*)h;
    }
}

// ht[b][c][j][8] -> htd[b][d][j] (d-major, j contiguous; zero-padded)
__global__ void transpose2_kernel()
{
    const int dg = blockIdx.x;     // 0..12 (8 d-rows each)
    const int b  = blockIdx.y;
    for (int u = threadIdx.x; u < 8 * JPAD; u += 256) {
        int dd = u / JPAD, jj = u - dd * JPAD;
        int d = dg * 8 + dd;
        __half v = __float2half(0.f);
        if (d < DD && jj < NN)
            v = ht_scratch[(((size_t)b * C14 + (d >> 3)) * NN + jj) * 8 + (d & 7)];
        htd_scratch[((size_t)b * DPAD + d) * JPAD + jj] = v;
    }
}

__global__ __launch_bounds__(256, 3)
void gnn_agg_kernel(const int* __restrict__ adj,
                    float* __restrict__ out)
{
    extern __shared__ float sm[];
    __half* gf = (__half*)sm;             // A fragments: [(mt*7+ks)*32+lane][8 halves]
    float*  pt = sm + OFF_PT;             // [NN][PTS] (first 8 used): alpha staging
    __half* pp = (__half*)(sm + OFF_PP);  // [8][PPS]: fp16 softmax weights, i-major
    __shared__ int kb_s[NN];              // nibble i: ksel(2b) | valid(bit2)

    const int b    = blockIdx.y;
    const int i0   = blockIdx.x * IT;
    const int tid  = threadIdx.x;
    const int w    = tid >> 5;
    const int lane = tid & 31;
    const int gid  = lane >> 2;      // 0..7
    const int tig  = lane & 3;       // 0..3

    // ---- kb table ----
    if (tid < NN) {
        unsigned kb = 0;
        const int* ap = adj + ((size_t)b * NN + i0) * NN + tid;
#pragma unroll
        for (int i = 0; i < IT; ++i) {
            int a = ap[(size_t)i * NN];
            unsigned valid = (a >= 1 && a <= 4) ? 4u : 0u;
            unsigned ksel = valid ? (unsigned)(a - 1) : 0u;
            kb |= (ksel | valid) << (4 * i);
        }
        kb_s[tid] = (int)kb;
    }

    // ---- pt pre-init to NEG; pp pre-init to 0 ----
    for (int u = tid; u < NN * 8; u += 256) {
        int jj = u >> 3, ii = u & 7;
        pt[jj * PTS + ii] = NEGV;
    }
    for (int u = tid; u < (8 * PPS) / 2; u += 256)
        ((unsigned*)pp)[u] = 0u;

    // ---- stage A fragments for score: gf[mt][ks][lane] in m16n8k16 A order ----
    for (int e = tid; e < 448; e += 256) {
        int mt = e / 224, rem = e - mt * 224;
        int ks = rem >> 5, l = rem & 31;
        int g8 = l >> 2, t4 = l & 3;
        int i  = i0 + g8;
        int cp = t4 * 2;
        int c8a = 2 * ks, c8b = 2 * ks + 1;
        __half2 hlo = *(const __half2*)(ht_scratch + (((size_t)b * C14 + c8a) * NN + i) * 8 + cp);
        __half2 hhi = *(const __half2*)(ht_scratch + (((size_t)b * C14 + c8b) * NN + i) * 8 + cp);
        int ka = 2 * mt, kb2 = 2 * mt + 1;
        __half2 alo_a = *(const __half2*)(ah_scratch + (c8a * 4 + ka)  * 8 + cp);
        __half2 alo_b = *(const __half2*)(ah_scratch + (c8a * 4 + kb2) * 8 + cp);
        __half2 ahi_a = *(const __half2*)(ah_scratch + (c8b * 4 + ka)  * 8 + cp);
        __half2 ahi_b = *(const __half2*)(ah_scratch + (c8b * 4 + kb2) * 8 + cp);
        __half2 pk[4];
        pk[0] = __hmul2(hlo, alo_a);
        pk[1] = __hmul2(hlo, alo_b);
        pk[2] = __hmul2(hhi, ahi_a);
        pk[3] = __hmul2(hhi, ahi_b);
        *(uint4*)(gf + (size_t)(mt * 7 + ks) * 32 * 8 + l * 8) = *(uint4*)pk;
    }
    __syncthreads();

    // ---- score via HMMA: C[32=(k,i), 200=j], split even/odd-ks chains ----
    const int mt = w & 1;
    unsigned aF[7][4];
#pragma unroll
    for (int ks = 0; ks < 7; ++ks)
        *(uint4*)aF[ks] = *(const uint4*)(gf + (size_t)(mt * 7 + ks) * 32 * 8 + lane * 8);

    const __half* htb = ht_scratch + (size_t)b * C14 * NN * 8;
    for (int nt = (w >> 1); nt < 25; nt += 4) {
        int jB = nt * 8 + gid;
        unsigned b0[7], b1[7];
#pragma unroll
        for (int ks = 0; ks < 7; ++ks) {
            b0[ks] = *(const unsigned*)(htb + ((size_t)(2 * ks)     * NN + jB) * 8 + tig * 2);
            b1[ks] = *(const unsigned*)(htb + ((size_t)(2 * ks + 1) * NN + jB) * 8 + tig * 2);
        }
        float cA0 = 0.f, cA1 = 0.f, cA2 = 0.f, cA3 = 0.f;
        float cB0 = 0.f, cB1 = 0.f, cB2 = 0.f, cB3 = 0.f;
#pragma unroll
        for (int ks = 0; ks < 7; ks += 2) {
            asm("mma.sync.aligned.m16n8k16.row.col.f32.f16.f16.f32 "
                "{%0,%1,%2,%3}, {%4,%5,%6,%7}, {%8,%9}, {%0,%1,%2,%3};"
                : "+f"(cA0), "+f"(cA1), "+f"(cA2), "+f"(cA3)
                : "r"(aF[ks][0]), "r"(aF[ks][1]), "r"(aF[ks][2]), "r"(aF[ks][3]),
                  "r"(b0[ks]), "r"(b1[ks]));
        }
#pragma unroll
        for (int ks = 1; ks < 7; ks += 2) {
            asm("mma.sync.aligned.m16n8k16.row.col.f32.f16.f16.f32 "
                "{%0,%1,%2,%3}, {%4,%5,%6,%7}, {%8,%9}, {%0,%1,%2,%3};"
                : "+f"(cB0), "+f"(cB1), "+f"(cB2), "+f"(cB3)
                : "r"(aF[ks][0]), "r"(aF[ks][1]), "r"(aF[ks][2]), "r"(aF[ks][3]),
                  "r"(b0[ks]), "r"(b1[ks]));
        }
        float c0 = cA0 + cB0, c1 = cA1 + cB1;
        float c2 = cA2 + cB2, c3 = cA3 + cB3;
        int j0 = nt * 8 + tig * 2;
        unsigned k0 = (unsigned)kb_s[j0]     >> (4 * gid);
        unsigned k1 = (unsigned)kb_s[j0 + 1] >> (4 * gid);
        unsigned ka = (unsigned)(2 * mt), kbv = ka + 1;
        if ((k0 & 4u) && (k0 & 3u) == ka)  pt[j0 * PTS + gid]       = (c0 >= 0.f) ? c0 : 0.2f * c0;
        if ((k1 & 4u) && (k1 & 3u) == ka)  pt[(j0 + 1) * PTS + gid] = (c1 >= 0.f) ? c1 : 0.2f * c1;
        if ((k0 & 4u) && (k0 & 3u) == kbv) pt[j0 * PTS + gid]       = (c2 >= 0.f) ? c2 : 0.2f * c2;
        if ((k1 & 4u) && (k1 & 3u) == kbv) pt[(j0 + 1) * PTS + gid] = (c3 >= 0.f) ? c3 : 0.2f * c3;
    }
    __syncthreads();

    // ---- softmax: warp w owns row i = w; writes fp16 weights to pp[i][j] ----
    {
        float al[7];
#pragma unroll
        for (int t = 0; t < 7; ++t) {
            int jj = lane + 32 * t;
            al[t] = (jj < NN) ? pt[jj * PTS + w] : NEGV;
        }
        float m = al[0];
#pragma unroll
        for (int t = 1; t < 7; ++t) m = fmaxf(m, al[t]);
#pragma unroll
        for (int off = 16; off > 0; off >>= 1)
            m = fmaxf(m, __shfl_xor_sync(0xffffffffu, m, off));

        float pv[7];
        float sum = 0.f;
#pragma unroll
        for (int t = 0; t < 7; ++t) {
            int jj = lane + 32 * t;
            float e = (jj < NN) ? __expf(al[t] - m) : 0.f;
            pv[t] = e;
            sum += e;
        }
#pragma unroll
        for (int off = 16; off > 0; off >>= 1)
            sum += __shfl_xor_sync(0xffffffffu, sum, off);
        float rinv = 1.f / sum;
#pragma unroll
        for (int t = 0; t < 7; ++t) {
            int jj = lane + 32 * t;
            if (jj < NN) pp[w * PPS + jj] = __float2half(pv[t] * rinv);
        }
    }
    __syncthreads();

    // ---- aggregation via HMMA: out[8,100] = p[8,200(pad208)] * h[200,100(pad104)] ----
    // A = pp (row-major, rows 8..15 zero), B = htd column d (col-major over j)
    unsigned pA0[13], pA1[13];
#pragma unroll
    for (int kt = 0; kt < 13; ++kt) {
        pA0[kt] = *(const unsigned*)(pp + gid * PPS + kt * 16 + tig * 2);
        pA1[kt] = *(const unsigned*)(pp + gid * PPS + kt * 16 + tig * 2 + 8);
    }

    for (int nt = w; nt < 13; nt += 8) {
        const __half* hb = htd_scratch + ((size_t)b * DPAD + nt * 8 + gid) * JPAD + tig * 2;
        unsigned hb0[13], hb1[13];
#pragma unroll
        for (int kt = 0; kt < 13; ++kt) {
            hb0[kt] = *(const unsigned*)(hb + kt * 16);
            hb1[kt] = *(const unsigned*)(hb + kt * 16 + 8);
        }
        float cA0 = 0.f, cA1 = 0.f, cA2 = 0.f, cA3 = 0.f;
        float cB0 = 0.f, cB1 = 0.f, cB2 = 0.f, cB3 = 0.f;
#pragma unroll
        for (int kt = 0; kt < 13; kt += 2) {
            asm("mma.sync.aligned.m16n8k16.row.col.f32.f16.f16.f32 "
                "{%0,%1,%2,%3}, {%4,%5,%6,%7}, {%8,%9}, {%0,%1,%2,%3};"
                : "+f"(cA0), "+f"(cA1), "+f"(cA2), "+f"(cA3)
                : "r"(pA0[kt]), "r"(0u), "r"(pA1[kt]), "r"(0u),
                  "r"(hb0[kt]), "r"(hb1[kt]));
        }
#pragma unroll
        for (int kt = 1; kt < 13; kt += 2) {
            asm("mma.sync.aligned.m16n8k16.row.col.f32.f16.f16.f32 "
                "{%0,%1,%2,%3}, {%4,%5,%6,%7}, {%8,%9}, {%0,%1,%2,%3};"
                : "+f"(cB0), "+f"(cB1), "+f"(cB2), "+f"(cB3)
                : "r"(pA0[kt]), "r"(0u), "r"(pA1[kt]), "r"(0u),
                  "r"(hb0[kt]), "r"(hb1[kt]));
        }
        // C: c0,c1 = (row gid = i, cols nt*8 + tig*2, +1); rows gid+8 discarded
        int d0 = nt * 8 + tig * 2;
        if (d0 < DD) {
            float2 o;
            o.x = cA0 + cB0;
            o.y = cA1 + cB1;
            *(float2*)(out + ((size_t)(b * NN + i0 + gid)) * DD + d0) = o;
        }
    }
}

extern "C" void kernel_launch(void* const* d_in, const int* in_sizes, int n_in,
                              void* d_out, int out_size)
{
    const int*   inputs = (const int*)d_in[0];
    const int*   adj    = (const int*)d_in[1];
    // d_in[2] = mask_item (unused by reference)
    const float* emb    = (const float*)d_in[3];
    const float* a0     = (const float*)d_in[4];
    const float* a1     = (const float*)d_in[5];
    const float* a2     = (const float*)d_in[6];
    const float* a3     = (const float*)d_in[7];
    float*       out    = (float*)d_out;

    cudaFuncSetAttribute(gnn_agg_kernel,
                         cudaFuncAttributeMaxDynamicSharedMemorySize,
                         SMEM_BYTES);

    // Phase 1: gather + fp16 transpose (ht, ah)
    dim3 tg(C14, BB);    // 14 x 32
    transpose_kernel<<<tg, 256>>>(inputs, emb, a0, a1, a2, a3);

    // Phase 1b: build d-major htd for agg B fragments
    dim3 tg2(13, BB);    // 13 x 32
    transpose2_kernel<<<tg2, 256>>>();

    // Phase 2: fused HMMA-score / softmax / HMMA-aggregate
    dim3 grid(NN / IT, BB);   // 25 x 32 = 800 blocks
    gnn_agg_kernel<<<grid, 256, SMEM_BYTES>>>(adj, out);
}

// round 13
// speedup vs baseline: 1.4303x; 1.0011x over previous
#include <cuda_runtime.h>
#include <cuda_fp16.h>

typedef unsigned long long ull;

// Problem constants (fixed by the dataset)
#define BB 32
#define NN 200
#define DD 100
#define IT 8              // i-rows per block
#define C14 14            // 8-half d-chunks per row (112 padded, score K)
#define DPAD 104          // padded d rows in htd
#define JPAD 208          // padded j cols in htd / pp (13 k16 tiles)
#define PTS 12            // pt row stride (floats)
#define PPS 216           // pp row stride (halves)
#define NEGV (-9e15f)

// smem (floats): gf(fp16) | pt(f32) | pp(fp16)
#define OFF_PT  1792                         // gf: 2*7*32*8 halves = 1792 floats
#define OFF_PP  (OFF_PT + NN*PTS)            // pt: 2400 floats
#define SMEM_FLOATS (OFF_PP + (8*PPS)/2)     // pp: 1728 halves = 864 floats
#define SMEM_BYTES  (SMEM_FLOATS*4)          // 20224 B

// fp16 transposed gathered embeddings: ht[b][c14][j][8 halves]
__device__ __half ht_scratch[(size_t)BB * C14 * NN * 8];
// fp16 edge weights: ah[c14][k][8 halves]
__device__ __half ah_scratch[C14 * 4 * 8];
// fp16 d-major embeddings for agg B-fragments: htd[b][d][j]
__device__ __half htd_scratch[(size_t)BB * DPAD * JPAD];

// ---- fused prep: gather emb -> ht (j-major chunks) + htd (d-major) + ah ----
// grid (9, BB): blocks jg=0..7 handle 25 j's each; jg==8 zero-pads j 200..207
__global__ __launch_bounds__(256)
void prep_kernel(const int* __restrict__ inputs,
                 const float* __restrict__ emb,
                 const float* __restrict__ a0,
                 const float* __restrict__ a1,
                 const float* __restrict__ a2,
                 const float* __restrict__ a3)
{
    __shared__ __half th[112][26];   // [d][r], r = j within this block's group
    const int jg   = blockIdx.x;
    const int b    = blockIdx.y;
    const int tid  = threadIdx.x;
    const int w    = tid >> 5;
    const int lane = tid & 31;

    if (jg == 8) {
        // zero-pad htd columns j = 200..207 (all d)
        for (int u = tid; u < DPAD * 8; u += 256) {
            int d = u >> 3, jj = NN + (u & 7);
            htd_scratch[((size_t)b * DPAD + d) * JPAD + jj] = __float2half(0.f);
        }
        return;
    }

    // zero the tile (covers d >= 100 padding)
    for (int u = tid; u < (112 * 26) / 2; u += 256)
        ((unsigned*)th)[u] = 0u;
    __syncthreads();

    const int j0 = jg * 25;
    for (int r = w; r < 25; r += 8) {
        int j = j0 + r;
        int id = inputs[b * NN + j];
        if (lane < 25) {
            float4 v = *(const float4*)(emb + (size_t)id * DD + 4 * lane);
            __half h4[4];
            h4[0] = __float2half(v.x); h4[1] = __float2half(v.y);
            h4[2] = __float2half(v.z); h4[3] = __float2half(v.w);
            // ht: chunk c = lane/2, 4-half offset (lane&1)*4 -> 8B store
            *(ull*)(ht_scratch + (((size_t)b * C14 + (lane >> 1)) * NN + j) * 8
                    + (lane & 1) * 4) = *(ull*)h4;
            int d = 4 * lane;
            th[d][r] = h4[0]; th[d + 1][r] = h4[1];
            th[d + 2][r] = h4[2]; th[d + 3][r] = h4[3];
        } else if (lane < 28) {
            // zero-pad ht d=100..111: lane25->(c12,+4), 26->(c13,+0), 27->(c13,+4)
            int c   = (lane == 25) ? 12 : 13;
            int off = (lane == 26) ? 0 : 4;
            *(ull*)(ht_scratch + (((size_t)b * C14 + c) * NN + j) * 8 + off) = 0ull;
        }
    }
    __syncthreads();

    // htd: warp w writes rows d = w, w+8, ... (25 halves contiguous per row)
    for (int d = w; d < DPAD; d += 8) {
        if (lane < 25)
            htd_scratch[((size_t)b * DPAD + d) * JPAD + j0 + lane] = th[d][lane];
    }

    // ah staging (once)
    if (jg == 0 && b == 0 && tid < 4) {
        const float* ak = (tid == 0) ? a0 : (tid == 1) ? a1 : (tid == 2) ? a2 : a3;
        for (int c = 0; c < C14; ++c) {
            __half h[8];
#pragma unroll
            for (int r = 0; r < 8; ++r) {
                int d = c * 8 + r;
                h[r] = __float2half(d < DD ? ak[d] : 0.f);
            }
            *(uint4*)(ah_scratch + (c * 4 + tid) * 8) = *(uint4*)h;
        }
    }
}

__global__ __launch_bounds__(256, 3)
void gnn_agg_kernel(const int* __restrict__ adj,
                    float* __restrict__ out)
{
    extern __shared__ float sm[];
    __half* gf = (__half*)sm;             // A fragments: [(mt*7+ks)*32+lane][8 halves]
    float*  pt = sm + OFF_PT;             // [NN][PTS] (first 8 used): alpha staging
    __half* pp = (__half*)(sm + OFF_PP);  // [8][PPS]: fp16 softmax weights, i-major
    __shared__ int kb_s[NN];              // nibble i: ksel(2b) | valid(bit2)

    const int b    = blockIdx.y;
    const int i0   = blockIdx.x * IT;
    const int tid  = threadIdx.x;
    const int w    = tid >> 5;
    const int lane = tid & 31;
    const int gid  = lane >> 2;      // 0..7
    const int tig  = lane & 3;       // 0..3

    // ---- kb table ----
    if (tid < NN) {
        unsigned kb = 0;
        const int* ap = adj + ((size_t)b * NN + i0) * NN + tid;
#pragma unroll
        for (int i = 0; i < IT; ++i) {
            int a = ap[(size_t)i * NN];
            unsigned valid = (a >= 1 && a <= 4) ? 4u : 0u;
            unsigned ksel = valid ? (unsigned)(a - 1) : 0u;
            kb |= (ksel | valid) << (4 * i);
        }
        kb_s[tid] = (int)kb;
    }

    // ---- pt pre-init to NEG; pp pre-init to 0 ----
    for (int u = tid; u < NN * 8; u += 256) {
        int jj = u >> 3, ii = u & 7;
        pt[jj * PTS + ii] = NEGV;
    }
    for (int u = tid; u < (8 * PPS) / 2; u += 256)
        ((unsigned*)pp)[u] = 0u;

    // ---- stage A fragments for score: gf[mt][ks][lane] in m16n8k16 A order ----
    for (int e = tid; e < 448; e += 256) {
        int mt = e / 224, rem = e - mt * 224;
        int ks = rem >> 5, l = rem & 31;
        int g8 = l >> 2, t4 = l & 3;
        int i  = i0 + g8;
        int cp = t4 * 2;
        int c8a = 2 * ks, c8b = 2 * ks + 1;
        __half2 hlo = *(const __half2*)(ht_scratch + (((size_t)b * C14 + c8a) * NN + i) * 8 + cp);
        __half2 hhi = *(const __half2*)(ht_scratch + (((size_t)b * C14 + c8b) * NN + i) * 8 + cp);
        int ka = 2 * mt, kb2 = 2 * mt + 1;
        __half2 alo_a = *(const __half2*)(ah_scratch + (c8a * 4 + ka)  * 8 + cp);
        __half2 alo_b = *(const __half2*)(ah_scratch + (c8a * 4 + kb2) * 8 + cp);
        __half2 ahi_a = *(const __half2*)(ah_scratch + (c8b * 4 + ka)  * 8 + cp);
        __half2 ahi_b = *(const __half2*)(ah_scratch + (c8b * 4 + kb2) * 8 + cp);
        __half2 pk[4];
        pk[0] = __hmul2(hlo, alo_a);
        pk[1] = __hmul2(hlo, alo_b);
        pk[2] = __hmul2(hhi, ahi_a);
        pk[3] = __hmul2(hhi, ahi_b);
        *(uint4*)(gf + (size_t)(mt * 7 + ks) * 32 * 8 + l * 8) = *(uint4*)pk;
    }
    __syncthreads();

    // ---- score via HMMA: C[32=(k,i), 200=j], split even/odd-ks chains ----
    const int mt = w & 1;
    unsigned aF[7][4];
#pragma unroll
    for (int ks = 0; ks < 7; ++ks)
        *(uint4*)aF[ks] = *(const uint4*)(gf + (size_t)(mt * 7 + ks) * 32 * 8 + lane * 8);

    const __half* htb = ht_scratch + (size_t)b * C14 * NN * 8;
    for (int nt = (w >> 1); nt < 25; nt += 4) {
        int jB = nt * 8 + gid;
        unsigned b0[7], b1[7];
#pragma unroll
        for (int ks = 0; ks < 7; ++ks) {
            b0[ks] = *(const unsigned*)(htb + ((size_t)(2 * ks)     * NN + jB) * 8 + tig * 2);
            b1[ks] = *(const unsigned*)(htb + ((size_t)(2 * ks + 1) * NN + jB) * 8 + tig * 2);
        }
        float cA0 = 0.f, cA1 = 0.f, cA2 = 0.f, cA3 = 0.f;
        float cB0 = 0.f, cB1 = 0.f, cB2 = 0.f, cB3 = 0.f;
#pragma unroll
        for (int ks = 0; ks < 7; ks += 2) {
            asm("mma.sync.aligned.m16n8k16.row.col.f32.f16.f16.f32 "
                "{%0,%1,%2,%3}, {%4,%5,%6,%7}, {%8,%9}, {%0,%1,%2,%3};"
                : "+f"(cA0), "+f"(cA1), "+f"(cA2), "+f"(cA3)
                : "r"(aF[ks][0]), "r"(aF[ks][1]), "r"(aF[ks][2]), "r"(aF[ks][3]),
                  "r"(b0[ks]), "r"(b1[ks]));
        }
#pragma unroll
        for (int ks = 1; ks < 7; ks += 2) {
            asm("mma.sync.aligned.m16n8k16.row.col.f32.f16.f16.f32 "
                "{%0,%1,%2,%3}, {%4,%5,%6,%7}, {%8,%9}, {%0,%1,%2,%3};"
                : "+f"(cB0), "+f"(cB1), "+f"(cB2), "+f"(cB3)
                : "r"(aF[ks][0]), "r"(aF[ks][1]), "r"(aF[ks][2]), "r"(aF[ks][3]),
                  "r"(b0[ks]), "r"(b1[ks]));
        }
        float c0 = cA0 + cB0, c1 = cA1 + cB1;
        float c2 = cA2 + cB2, c3 = cA3 + cB3;
        int j0 = nt * 8 + tig * 2;
        unsigned k0 = (unsigned)kb_s[j0]     >> (4 * gid);
        unsigned k1 = (unsigned)kb_s[j0 + 1] >> (4 * gid);
        unsigned ka = (unsigned)(2 * mt), kbv = ka + 1;
        if ((k0 & 4u) && (k0 & 3u) == ka)  pt[j0 * PTS + gid]       = (c0 >= 0.f) ? c0 : 0.2f * c0;
        if ((k1 & 4u) && (k1 & 3u) == ka)  pt[(j0 + 1) * PTS + gid] = (c1 >= 0.f) ? c1 : 0.2f * c1;
        if ((k0 & 4u) && (k0 & 3u) == kbv) pt[j0 * PTS + gid]       = (c2 >= 0.f) ? c2 : 0.2f * c2;
        if ((k1 & 4u) && (k1 & 3u) == kbv) pt[(j0 + 1) * PTS + gid] = (c3 >= 0.f) ? c3 : 0.2f * c3;
    }
    __syncthreads();

    // ---- softmax: warp w owns row i = w; writes fp16 weights to pp[i][j] ----
    {
        float al[7];
#pragma unroll
        for (int t = 0; t < 7; ++t) {
            int jj = lane + 32 * t;
            al[t] = (jj < NN) ? pt[jj * PTS + w] : NEGV;
        }
        float m = al[0];
#pragma unroll
        for (int t = 1; t < 7; ++t) m = fmaxf(m, al[t]);
#pragma unroll
        for (int off = 16; off > 0; off >>= 1)
            m = fmaxf(m, __shfl_xor_sync(0xffffffffu, m, off));

        float pv[7];
        float sum = 0.f;
#pragma unroll
        for (int t = 0; t < 7; ++t) {
            int jj = lane + 32 * t;
            float e = (jj < NN) ? __expf(al[t] - m) : 0.f;
            pv[t] = e;
            sum += e;
        }
#pragma unroll
        for (int off = 16; off > 0; off >>= 1)
            sum += __shfl_xor_sync(0xffffffffu, sum, off);
        float rinv = 1.f / sum;
#pragma unroll
        for (int t = 0; t < 7; ++t) {
            int jj = lane + 32 * t;
            if (jj < NN) pp[w * PPS + jj] = __float2half(pv[t] * rinv);
        }
    }
    __syncthreads();

    // ---- aggregation via HMMA: out[8,100] = p[8,208] * h[208,104] ----
    unsigned pA0[13], pA1[13];
#pragma unroll
    for (int kt = 0; kt < 13; ++kt) {
        pA0[kt] = *(const unsigned*)(pp + gid * PPS + kt * 16 + tig * 2);
        pA1[kt] = *(const unsigned*)(pp + gid * PPS + kt * 16 + tig * 2 + 8);
    }

    for (int nt = w; nt < 13; nt += 8) {
        const __half* hb = htd_scratch + ((size_t)b * DPAD + nt * 8 + gid) * JPAD + tig * 2;
        unsigned hb0[13], hb1[13];
#pragma unroll
        for (int kt = 0; kt < 13; ++kt) {
            hb0[kt] = *(const unsigned*)(hb + kt * 16);
            hb1[kt] = *(const unsigned*)(hb + kt * 16 + 8);
        }
        float cA0 = 0.f, cA1 = 0.f, cA2 = 0.f, cA3 = 0.f;
        float cB0 = 0.f, cB1 = 0.f, cB2 = 0.f, cB3 = 0.f;
#pragma unroll
        for (int kt = 0; kt < 13; kt += 2) {
            asm("mma.sync.aligned.m16n8k16.row.col.f32.f16.f16.f32 "
                "{%0,%1,%2,%3}, {%4,%5,%6,%7}, {%8,%9}, {%0,%1,%2,%3};"
                : "+f"(cA0), "+f"(cA1), "+f"(cA2), "+f"(cA3)
                : "r"(pA0[kt]), "r"(0u), "r"(pA1[kt]), "r"(0u),
                  "r"(hb0[kt]), "r"(hb1[kt]));
        }
#pragma unroll
        for (int kt = 1; kt < 13; kt += 2) {
            asm("mma.sync.aligned.m16n8k16.row.col.f32.f16.f16.f32 "
                "{%0,%1,%2,%3}, {%4,%5,%6,%7}, {%8,%9}, {%0,%1,%2,%3};"
                : "+f"(cB0), "+f"(cB1), "+f"(cB2), "+f"(cB3)
                : "r"(pA0[kt]), "r"(0u), "r"(pA1[kt]), "r"(0u),
                  "r"(hb0[kt]), "r"(hb1[kt]));
        }
        int d0 = nt * 8 + tig * 2;
        if (d0 < DD) {
            float2 o;
            o.x = cA0 + cB0;
            o.y = cA1 + cB1;
            *(float2*)(out + ((size_t)(b * NN + i0 + gid)) * DD + d0) = o;
        }
    }
}

extern "C" void kernel_launch(void* const* d_in, const int* in_sizes, int n_in,
                              void* d_out, int out_size)
{
    const int*   inputs = (const int*)d_in[0];
    const int*   adj    = (const int*)d_in[1];
    // d_in[2] = mask_item (unused by reference)
    const float* emb    = (const float*)d_in[3];
    const float* a0     = (const float*)d_in[4];
    const float* a1     = (const float*)d_in[5];
    const float* a2     = (const float*)d_in[6];
    const float* a3     = (const float*)d_in[7];
    float*       out    = (float*)d_out;

    cudaFuncSetAttribute(gnn_agg_kernel,
                         cudaFuncAttributeMaxDynamicSharedMemorySize,
                         SMEM_BYTES);

    // Phase 1: fused gather + both fp16 transposes (ht, htd, ah)
    dim3 pg(9, BB);      // 9 x 32 = 288 blocks
    prep_kernel<<<pg, 256>>>(inputs, emb, a0, a1, a2, a3);

    // Phase 2: fused HMMA-score / softmax / HMMA-aggregate
    dim3 grid(NN / IT, BB);   // 25 x 32 = 800 blocks
    gnn_agg_kernel<<<grid, 256, SMEM_BYTES>>>(adj, out);
}